// round 9
// baseline (speedup 1.0000x reference)
#include <cuda_runtime.h>
#include <cuda_fp16.h>
#include <cstdint>
#include <cstddef>

#define NN 100000
#define EE 800000

// ---------------- packed f32x2 helpers ----------------
union F4U { float4 f; unsigned long long u[2]; };

__device__ __forceinline__ unsigned long long pack2(float a) {
    unsigned long long r;
    asm("mov.b64 %0, {%1,%1};" : "=l"(r) : "f"(a));
    return r;
}
__device__ __forceinline__ void fma2(unsigned long long& d,
                                     unsigned long long a,
                                     unsigned long long b) {
    asm("fma.rn.f32x2 %0, %1, %2, %0;" : "+l"(d) : "l"(a), "l"(b));
}

// ---------------- device scratch (static: no runtime allocation) ----------------
__device__ __half g_keyh[(size_t)NN * 128];
__device__ __half g_qryh[(size_t)NN * 128];
__device__ __half g_qkh [(size_t)NN * 64];
__device__ __half g_valh[(size_t)NN * 128];
__device__ float  g_ex [(size_t)EE * 4];
__device__ float  g_den[(size_t)NN * 4];

// ---------------- K1: node kernel ----------------
// 8 warps/block, lane = node, 3 blocks/SM (24 warps).
// Two phases reuse ONE 2-matrix smem slot:
//   Phase A: wk,wv resident -> key,value.  Phase B: wq,wsk resident -> query,skip,qk.
__global__ void __launch_bounds__(256, 3)
k_node(const float* __restrict__ x, const float* __restrict__ rbf,
       const float* __restrict__ w_rbf0, const float* __restrict__ w_rbf1,
       const float* __restrict__ wk, const float* __restrict__ bk,
       const float* __restrict__ wq, const float* __restrict__ bq,
       const float* __restrict__ wv, const float* __restrict__ bv,
       const float* __restrict__ wsk, const float* __restrict__ bsk,
       const float* __restrict__ wek, float* __restrict__ out) {
    __shared__ float sh[12096];
    float* s_w0  = sh;            // [32,128] slot 0: wk then wq
    float* s_w1  = sh + 4096;     // [32,128] slot 1: wv then wsk
    float* s_ekT = sh + 8192;     // ekT[j*16+d] = wek[d*128+j]  (2048)
    float* s_rc  = sh + 10240;    // combined rbf weights [42,32] (1344)
    float* s_b   = sh + 11584;    // bk | bq | bv | bskip         (512)

    const int tid = threadIdx.x;
    // ---- phase A weight load ----
    for (int i = tid; i < 4096; i += 256) {
        s_w0[i] = wk[i]; s_w1[i] = wv[i];
    }
    for (int i = tid; i < 1344; i += 256) {
        int d = i >> 5, c = i & 31;
        float s = 0.f;
#pragma unroll
        for (int m = 0; m < 32; m++) s += w_rbf0[d * 32 + m] * w_rbf1[m * 32 + c];
        s_rc[i] = s;
    }
    for (int i = tid; i < 512; i += 256) {
        int w = i >> 7, c = i & 127;
        s_b[i] = (w == 0) ? bk[c] : (w == 1) ? bq[c] : (w == 2) ? bv[c] : bsk[c];
    }
    __syncthreads();

    const int warpid = tid >> 5;
    const int lane   = tid & 31;
    int tile = blockIdx.x * 8 + warpid;
    if (tile >= (NN / 32)) tile = NN / 32 - 1;   // clamp: duplicate work, identical stores
    const int n = tile * 32 + lane;

    // ---- load this lane's rbf row (8B-aligned float2 loads) ----
    float rr[42];
    {
        const float2* rp = (const float2*)(rbf + (size_t)n * 42);
#pragma unroll
        for (int i = 0; i < 21; i++) {
            float2 t = __ldg(rp + i);
            rr[2 * i] = t.x; rr[2 * i + 1] = t.y;
        }
    }

    // ---- rbf_filter (f32x2 on smem broadcasts) ----
    F4U fil[8];
#pragma unroll
    for (int i = 0; i < 8; i++) fil[i].f = make_float4(0.f, 0.f, 0.f, 0.f);
#pragma unroll 6
    for (int d = 0; d < 42; d++) {
        unsigned long long r2 = pack2(rr[d]);
#pragma unroll
        for (int t8 = 0; t8 < 8; t8++) {
            F4U w; w.f = *(const float4*)&s_rc[d * 32 + t8 * 4];
            fma2(fil[t8].u[0], r2, w.u[0]);
            fma2(fil[t8].u[1], r2, w.u[1]);
        }
    }

    // ---- xs = filter * x ----
    float xs[32];
    {
        const float4* xp = (const float4*)(x + (size_t)n * 32);
#pragma unroll
        for (int i = 0; i < 8; i++) {
            float4 xv = __ldg(xp + i);
            xs[i * 4 + 0] = fil[i].f.x * xv.x;
            xs[i * 4 + 1] = fil[i].f.y * xv.y;
            xs[i * 4 + 2] = fil[i].f.z * xv.z;
            xs[i * 4 + 3] = fil[i].f.w * xv.w;
        }
    }

    // ---- Phase A: key + value (from xs) ----
#pragma unroll 1
    for (int ct = 0; ct < 32; ct++) {
        const int ch = ct * 4;
        F4U ak, av;
        ak.f = *(const float4*)&s_b[ch];
        av.f = *(const float4*)&s_b[256 + ch];
#pragma unroll 8
        for (int c = 0; c < 32; c++) {
            F4U w1, w3;
            w1.f = *(const float4*)&s_w0[c * 128 + ch];
            w3.f = *(const float4*)&s_w1[c * 128 + ch];
            unsigned long long a2 = pack2(xs[c]);
            fma2(ak.u[0], a2, w1.u[0]); fma2(ak.u[1], a2, w1.u[1]);
            fma2(av.u[0], a2, w3.u[0]); fma2(av.u[1], a2, w3.u[1]);
        }
        __half2 h0 = __floats2half2_rn(ak.f.x, ak.f.y);
        __half2 h1 = __floats2half2_rn(ak.f.z, ak.f.w);
        *(uint2*)&g_keyh[(size_t)n * 128 + ch] =
            make_uint2(*(unsigned*)&h0, *(unsigned*)&h1);
        __half2 v0 = __floats2half2_rn(av.f.x, av.f.y);
        __half2 v1 = __floats2half2_rn(av.f.z, av.f.w);
        *(uint2*)&g_valh[(size_t)n * 128 + ch] =
            make_uint2(*(unsigned*)&v0, *(unsigned*)&v1);
    }

    // ---- phase switch: reload weight slots with wq / wsk + ekT ----
    __syncthreads();
    for (int i = tid; i < 4096; i += 256) {
        s_w0[i] = wq[i]; s_w1[i] = wsk[i];
    }
    for (int i = tid; i < 2048; i += 256) {
        int j = i >> 4, d = i & 15;
        s_ekT[i] = wek[d * 128 + j];
    }
    __syncthreads();

    // ---- reload x row (L1/L2-hot) ----
    float xr[32];
    {
        const float4* xp = (const float4*)(x + (size_t)n * 32);
#pragma unroll
        for (int i = 0; i < 8; i++) {
            float4 xv = __ldg(xp + i);
            xr[i * 4 + 0] = xv.x; xr[i * 4 + 1] = xv.y;
            xr[i * 4 + 2] = xv.z; xr[i * 4 + 3] = xv.w;
        }
    }

    // ---- Phase B: query + skip + folded qk ----
    unsigned long long qk2[8];
#pragma unroll 1
    for (int ct = 0; ct < 32; ct++) {
        const int ch = ct * 4;
        if ((ct & 7) == 0) {
#pragma unroll
            for (int i = 0; i < 8; i++) qk2[i] = 0ull;
        }
        F4U aq, as2;
        aq.f  = *(const float4*)&s_b[128 + ch];
        as2.f = *(const float4*)&s_b[384 + ch];
#pragma unroll 8
        for (int c = 0; c < 32; c++) {
            F4U w2, w4;
            w2.f = *(const float4*)&s_w0[c * 128 + ch];
            w4.f = *(const float4*)&s_w1[c * 128 + ch];
            unsigned long long b2 = pack2(xr[c]);
            fma2(aq.u[0],  b2, w2.u[0]); fma2(aq.u[1],  b2, w2.u[1]);
            fma2(as2.u[0], b2, w4.u[0]); fma2(as2.u[1], b2, w4.u[1]);
        }
        __half2 q0 = __floats2half2_rn(aq.f.x, aq.f.y);
        __half2 q1 = __floats2half2_rn(aq.f.z, aq.f.w);
        *(uint2*)&g_qryh[(size_t)n * 128 + ch] =
            make_uint2(*(unsigned*)&q0, *(unsigned*)&q1);
        *(float4*)&out[(size_t)n * 128 + ch] = as2.f;

        float qa[4] = {aq.f.x, aq.f.y, aq.f.z, aq.f.w};
#pragma unroll
        for (int u = 0; u < 4; u++) {
            unsigned long long q2 = pack2(qa[u]);
#pragma unroll
            for (int dt = 0; dt < 4; dt++) {
                F4U ekv; ekv.f = *(const float4*)&s_ekT[(ch + u) * 16 + dt * 4];
                fma2(qk2[dt * 2],     q2, ekv.u[0]);
                fma2(qk2[dt * 2 + 1], q2, ekv.u[1]);
            }
        }
        if ((ct & 7) == 7) {
            const int h = ct >> 3;
            unsigned uu[8];
#pragma unroll
            for (int i = 0; i < 8; i++) {
                F4U tmp; tmp.u[0] = qk2[i]; tmp.u[1] = 0ull;
                __half2 p = __floats2half2_rn(tmp.f.x, tmp.f.y);
                uu[i] = *(unsigned*)&p;
            }
            *(uint4*)&g_qkh[(size_t)n * 64 + h * 16] =
                make_uint4(uu[0], uu[1], uu[2], uu[3]);
            *(uint4*)&g_qkh[(size_t)n * 64 + h * 16 + 8] =
                make_uint4(uu[4], uu[5], uu[6], uu[7]);
        }
    }
    *(float4*)&g_den[(size_t)n * 4] = make_float4(0.f, 0.f, 0.f, 0.f);
}

// ---------------- K2: edge alpha (8 lanes/edge, 4 edges/warp, fp16 gathers) ----------------
__global__ void __launch_bounds__(256)
k_alpha(const float* __restrict__ ea, const int* __restrict__ ei) {
    const int gw   = (blockIdx.x * blockDim.x + threadIdx.x) >> 5;
    const int lane = threadIdx.x & 31;
    const int g = lane >> 3, t = lane & 7;
    const int e = gw * 4 + g;
    if (e >= EE) return;
    const int src = ei[e];
    const int dst = ei[EE + e];
    const int h = t >> 1, half = t & 1;

    const uint4* qp = (const uint4*)(g_qryh + (size_t)dst * 128 + h * 32 + half * 16);
    const uint4* kp = (const uint4*)(g_keyh + (size_t)src * 128 + h * 32 + half * 16);
    float s = 0.f;
#pragma unroll
    for (int b = 0; b < 2; b++) {
        uint4 qv = qp[b], kv = kp[b];
        const __half2* qh = (const __half2*)&qv;
        const __half2* kh = (const __half2*)&kv;
#pragma unroll
        for (int i = 0; i < 4; i++) {
            float2 q2 = __half22float2(qh[i]);
            float2 k2 = __half22float2(kh[i]);
            s += q2.x * k2.x + q2.y * k2.y;
        }
    }
    uint4 qkv = *(const uint4*)(g_qkh + (size_t)dst * 64 + h * 16 + half * 8);
    const __half2* qkh = (const __half2*)&qkv;
    const float4* eap = (const float4*)(ea + (size_t)e * 16 + half * 8);
    float4 e0 = eap[0], e1 = eap[1];
    float2 a;
    a = __half22float2(qkh[0]); s += a.x * e0.x + a.y * e0.y;
    a = __half22float2(qkh[1]); s += a.x * e0.z + a.y * e0.w;
    a = __half22float2(qkh[2]); s += a.x * e1.x + a.y * e1.y;
    a = __half22float2(qkh[3]); s += a.x * e1.z + a.y * e1.w;

    s += __shfl_xor_sync(0xffffffffu, s, 1);
    if (half == 0) {
        float ex = __expf(s * 0.17677669529663687f);  // 1/sqrt(32)
        g_ex[(size_t)e * 4 + h] = ex;
        atomicAdd(&g_den[(size_t)dst * 4 + h], ex);
    }
}

// ---------------- K3: message + aggregation (8 lanes/edge, 4 edges/warp, f32x2) ----------------
__global__ void __launch_bounds__(256, 4)
k_msg(const float* __restrict__ ea, const float* __restrict__ sbf,
      const int* __restrict__ ei, const float* __restrict__ wev,
      const float* __restrict__ w_sbf0, const float* __restrict__ w_sbf1,
      float* __restrict__ out) {
    __shared__ float s_ev[16 * 128];
    __shared__ float s_sc[16 * 32];
    __shared__ float s_buf[8][368];   // per warp: sbf 4 edges x 64 @pitch72 (=288), ea 4x16 @pitch20 (=80)

    for (int i = threadIdx.x; i < 2048; i += 256) s_ev[i] = wev[i];
    for (int i = threadIdx.x; i < 512;  i += 256) {
        int d = i >> 5, c = i & 31;
        float s = 0.f;
#pragma unroll
        for (int m = 0; m < 32; m++) s += w_sbf0[d * 32 + m] * w_sbf1[m * 32 + c];
        s_sc[i] = s;
    }
    __syncthreads();

    const int warpid = threadIdx.x >> 5;
    const int lane   = threadIdx.x & 31;
    const int g = lane >> 3, t = lane & 7;
    const int warps_total = gridDim.x * 8;
    float* sb = s_buf[warpid];

    for (int tile = blockIdx.x * 8 + warpid; tile < EE / 4; tile += warps_total) {
        const int base = tile * 4;
        // stage sbf (4 edges x 64 floats, contiguous in gmem), pitch 72 keeps 16B alignment
        const float4* sp = (const float4*)(sbf + (size_t)base * 64);
        {
            int idx = lane * 4;                // elems 0..127
            *(float4*)&sb[(idx >> 6) * 72 + (idx & 63)] = sp[lane];
            idx = 128 + lane * 4;              // elems 128..255
            *(float4*)&sb[(idx >> 6) * 72 + (idx & 63)] = sp[32 + lane];
        }
        if (lane < 16) {
            float4 v = ((const float4*)(ea + (size_t)base * 16))[lane];
            *(float4*)&sb[288 + (lane >> 2) * 20 + (lane & 3) * 4] = v;
        }
        __syncwarp();

        const int e   = base + g;
        const int src = ei[e];
        const int dst = ei[EE + e];
        float4 exv = *(const float4*)&g_ex[(size_t)e * 4];
        float4 dnv = *(const float4*)&g_den[(size_t)dst * 4];

        // ---- hoist all 4 value gathers (fp16, MLP=4, hidden under the FMA loop) ----
        const size_t vbase = (size_t)src * 128;
        uint2 vh[4];
#pragma unroll
        for (int j = 0; j < 4; j++)
            vh[j] = *(const uint2*)&g_valh[vbase + j * 32 + t * 4];

        float av_[4];
        av_[0] = __fdividef(exv.x, dnv.x + 1e-16f);
        av_[1] = __fdividef(exv.y, dnv.y + 1e-16f);
        av_[2] = __fdividef(exv.z, dnv.z + 1e-16f);
        av_[3] = __fdividef(exv.w, dnv.w + 1e-16f);

        // accumulate edge_val (aev) and sbf_filter (af) with packed f32x2 FMA
        unsigned long long aev2[8], af2[8];
#pragma unroll
        for (int i = 0; i < 8; i++) { aev2[i] = 0ull; af2[i] = 0ull; }
#pragma unroll 4
        for (int d = 0; d < 16; d++) {
            unsigned long long sv2 = pack2(sb[288 + g * 20 + d]);
            F4U w2; w2.f = *(const float4*)&s_sc[d * 32 + t * 4];
#pragma unroll
            for (int j = 0; j < 4; j++) {
                unsigned long long sb2 = pack2(sb[g * 72 + j * 16 + d]);
                F4U w1; w1.f = *(const float4*)&s_ev[d * 128 + j * 32 + t * 4];
                fma2(aev2[j * 2],     sv2, w1.u[0]);
                fma2(aev2[j * 2 + 1], sv2, w1.u[1]);
                fma2(af2[j * 2],      sb2, w2.u[0]);
                fma2(af2[j * 2 + 1],  sb2, w2.u[1]);
            }
        }

        const size_t obase = (size_t)dst * 128;
#pragma unroll
        for (int j = 0; j < 4; j++) {
            F4U aev, af;
            aev.u[0] = aev2[j * 2]; aev.u[1] = aev2[j * 2 + 1];
            af.u[0]  = af2[j * 2];  af.u[1]  = af2[j * 2 + 1];
            float2 vlo = __half22float2(*(const __half2*)&vh[j].x);
            float2 vhi = __half22float2(*(const __half2*)&vh[j].y);
            const float aj = av_[j];
            float mx = (vlo.x + aev.f.x) * aj * af.f.x;
            float my = (vlo.y + aev.f.y) * aj * af.f.y;
            float mz = (vhi.x + aev.f.z) * aj * af.f.z;
            float mw = (vhi.y + aev.f.w) * aj * af.f.w;
            float* op = out + obase + j * 32 + t * 4;
            asm volatile("red.global.add.v4.f32 [%0], {%1,%2,%3,%4};"
                         :: "l"(op), "f"(mx), "f"(my), "f"(mz), "f"(mw) : "memory");
        }
        __syncwarp();
    }
}

// ---------------- launcher ----------------
extern "C" void kernel_launch(void* const* d_in, const int* in_sizes, int n_in,
                              void* d_out, int out_size) {
    const float* x        = (const float*)d_in[0];
    const float* edge_attr= (const float*)d_in[1];
    const float* rbf      = (const float*)d_in[2];
    const float* sbf      = (const float*)d_in[3];
    const float* w_rbf0   = (const float*)d_in[4];
    const float* w_rbf1   = (const float*)d_in[5];
    const float* w_sbf0   = (const float*)d_in[6];
    const float* w_sbf1   = (const float*)d_in[7];
    const float* w_ek     = (const float*)d_in[8];
    const float* w_ev     = (const float*)d_in[9];
    const float* w_k      = (const float*)d_in[10];
    const float* b_k      = (const float*)d_in[11];
    const float* w_q      = (const float*)d_in[12];
    const float* b_q      = (const float*)d_in[13];
    const float* w_v      = (const float*)d_in[14];
    const float* b_v      = (const float*)d_in[15];
    const float* w_skip   = (const float*)d_in[16];
    const float* b_skip   = (const float*)d_in[17];
    const int*   edge_index = (const int*)d_in[18];
    float* out = (float*)d_out;

    const int k1_blocks = (NN / 32 + 7) / 8;   // 391
    k_node<<<k1_blocks, 256>>>(
        x, rbf, w_rbf0, w_rbf1, w_k, b_k, w_q, b_q, w_v, b_v,
        w_skip, b_skip, w_ek, out);

    k_alpha<<<EE / 4 / 8, 256>>>(edge_attr, edge_index);

    k_msg<<<1184, 256>>>(edge_attr, sbf, edge_index, w_ev,
                         w_sbf0, w_sbf1, out);
}

// round 11
// speedup vs baseline: 1.0581x; 1.0581x over previous
#include <cuda_runtime.h>
#include <cuda_fp16.h>
#include <cstdint>
#include <cstddef>

#define NN 100000
#define EE 800000
#define SCAN_BLOCKS 98   // 98*1024 >= NN

// ---------------- packed f32x2 helpers ----------------
union F4U { float4 f; unsigned long long u[2]; };

__device__ __forceinline__ unsigned long long pack2(float a) {
    unsigned long long r;
    asm("mov.b64 %0, {%1,%1};" : "=l"(r) : "f"(a));
    return r;
}
__device__ __forceinline__ void fma2(unsigned long long& d,
                                     unsigned long long a,
                                     unsigned long long b) {
    asm("fma.rn.f32x2 %0, %1, %2, %0;" : "+l"(d) : "l"(a), "l"(b));
}

// ---------------- device scratch (static: no runtime allocation) ----------------
__device__ __half g_keyh[(size_t)NN * 128];
__device__ __half g_qryh[(size_t)NN * 128];
__device__ __half g_qkh [(size_t)NN * 64];
__device__ __half g_valh[(size_t)NN * 128];
__device__ float  g_ex [(size_t)EE * 4];
__device__ float  g_den[(size_t)NN * 4];
__device__ int    g_cnt [NN];
__device__ int    g_woff[NN];
__device__ int    g_part[SCAN_BLOCKS];
__device__ int    g_perm[EE];

// ---------------- sort kernels: counting sort of edges by dst ----------------
__global__ void k_zero() {
    int i = blockIdx.x * 256 + threadIdx.x;
    if (i < NN) g_cnt[i] = 0;
}

__global__ void k_hist(const int* __restrict__ ei) {
    int e = blockIdx.x * 256 + threadIdx.x;
    if (e < EE) atomicAdd(&g_cnt[ei[EE + e]], 1);
}

__global__ void k_scan1() {
    __shared__ int s[1024];
    int tid = threadIdx.x;
    int idx = blockIdx.x * 1024 + tid;
    s[tid] = (idx < NN) ? g_cnt[idx] : 0;
    __syncthreads();
    for (int off = 512; off >= 1; off >>= 1) {
        if (tid < off) s[tid] += s[tid + off];
        __syncthreads();
    }
    if (tid == 0) g_part[blockIdx.x] = s[0];
}

__global__ void k_scan2() {
    __shared__ int s[1024];
    __shared__ int sp[128];
    __shared__ int boff;
    int tid = threadIdx.x, b = blockIdx.x;
    if (tid < SCAN_BLOCKS) sp[tid] = g_part[tid];
    __syncthreads();
    if (tid == 0) { int a = 0; for (int k = 0; k < b; k++) a += sp[k]; boff = a; }
    int idx = b * 1024 + tid;
    int v = (idx < NN) ? g_cnt[idx] : 0;
    s[tid] = v;
    __syncthreads();
    for (int off = 1; off < 1024; off <<= 1) {
        int t2 = (tid >= off) ? s[tid - off] : 0;
        __syncthreads();
        s[tid] += t2;
        __syncthreads();
    }
    if (idx < NN) g_woff[idx] = boff + s[tid] - v;   // exclusive prefix
}

__global__ void k_scatter(const int* __restrict__ ei) {
    int e = blockIdx.x * 256 + threadIdx.x;
    if (e < EE) {
        int dst = ei[EE + e];
        int pos = atomicAdd(&g_woff[dst], 1);
        g_perm[pos] = e;
    }
}

// ---------------- K1: node kernel (R8-proven: 81KB smem, 2 blocks/SM) ----------------
#define K1_SMEM_FLOATS 20288

__global__ void __launch_bounds__(256, 2)
k_node(const float* __restrict__ x, const float* __restrict__ rbf,
       const float* __restrict__ w_rbf0, const float* __restrict__ w_rbf1,
       const float* __restrict__ wk, const float* __restrict__ bk,
       const float* __restrict__ wq, const float* __restrict__ bq,
       const float* __restrict__ wv, const float* __restrict__ bv,
       const float* __restrict__ wsk, const float* __restrict__ bsk,
       const float* __restrict__ wek, float* __restrict__ out) {
    extern __shared__ float sh[];
    float* s_wk  = sh;
    float* s_wq  = sh + 4096;
    float* s_wv  = sh + 8192;
    float* s_ws  = sh + 12288;
    float* s_ekT = sh + 16384;
    float* s_rc  = sh + 18432;
    float* s_b   = sh + 19776;

    const int tid = threadIdx.x;
    for (int i = tid; i < 4096; i += 256) {
        s_wk[i] = wk[i]; s_wq[i] = wq[i]; s_wv[i] = wv[i]; s_ws[i] = wsk[i];
    }
    for (int i = tid; i < 2048; i += 256) {
        int j = i >> 4, d = i & 15;
        s_ekT[i] = wek[d * 128 + j];
    }
    for (int i = tid; i < 1344; i += 256) {
        int d = i >> 5, c = i & 31;
        float s = 0.f;
#pragma unroll
        for (int m = 0; m < 32; m++) s += w_rbf0[d * 32 + m] * w_rbf1[m * 32 + c];
        s_rc[i] = s;
    }
    for (int i = tid; i < 512; i += 256) {
        int w = i >> 7, c = i & 127;
        s_b[i] = (w == 0) ? bk[c] : (w == 1) ? bq[c] : (w == 2) ? bv[c] : bsk[c];
    }
    __syncthreads();

    const int warpid = tid >> 5;
    const int lane   = tid & 31;
    const int tile   = blockIdx.x * 8 + warpid;
    if (tile >= (NN / 32)) return;
    const int n = tile * 32 + lane;

    float rr[42];
    {
        const float2* rp = (const float2*)(rbf + (size_t)n * 42);
#pragma unroll
        for (int i = 0; i < 21; i++) {
            float2 t = __ldg(rp + i);
            rr[2 * i] = t.x; rr[2 * i + 1] = t.y;
        }
    }

    F4U fil[8];
#pragma unroll
    for (int i = 0; i < 8; i++) fil[i].f = make_float4(0.f, 0.f, 0.f, 0.f);
#pragma unroll
    for (int d = 0; d < 42; d++) {
        unsigned long long r2 = pack2(rr[d]);
#pragma unroll
        for (int t8 = 0; t8 < 8; t8++) {
            F4U w; w.f = *(const float4*)&s_rc[d * 32 + t8 * 4];
            fma2(fil[t8].u[0], r2, w.u[0]);
            fma2(fil[t8].u[1], r2, w.u[1]);
        }
    }

    float xs[32];
    {
        const float4* xp = (const float4*)(x + (size_t)n * 32);
#pragma unroll
        for (int i = 0; i < 8; i++) {
            float4 xv = __ldg(xp + i);
            xs[i * 4 + 0] = fil[i].f.x * xv.x;
            xs[i * 4 + 1] = fil[i].f.y * xv.y;
            xs[i * 4 + 2] = fil[i].f.z * xv.z;
            xs[i * 4 + 3] = fil[i].f.w * xv.w;
        }
    }

    // ---- Pass A: key + value ----
#pragma unroll 1
    for (int ct = 0; ct < 32; ct++) {
        const int ch = ct * 4;
        F4U ak, av;
        ak.f = *(const float4*)&s_b[ch];
        av.f = *(const float4*)&s_b[256 + ch];
#pragma unroll
        for (int c = 0; c < 32; c++) {
            F4U w1, w3;
            w1.f = *(const float4*)&s_wk[c * 128 + ch];
            w3.f = *(const float4*)&s_wv[c * 128 + ch];
            unsigned long long a2 = pack2(xs[c]);
            fma2(ak.u[0], a2, w1.u[0]); fma2(ak.u[1], a2, w1.u[1]);
            fma2(av.u[0], a2, w3.u[0]); fma2(av.u[1], a2, w3.u[1]);
        }
        __half2 h0 = __floats2half2_rn(ak.f.x, ak.f.y);
        __half2 h1 = __floats2half2_rn(ak.f.z, ak.f.w);
        *(uint2*)&g_keyh[(size_t)n * 128 + ch] =
            make_uint2(*(unsigned*)&h0, *(unsigned*)&h1);
        __half2 v0 = __floats2half2_rn(av.f.x, av.f.y);
        __half2 v1 = __floats2half2_rn(av.f.z, av.f.w);
        *(uint2*)&g_valh[(size_t)n * 128 + ch] =
            make_uint2(*(unsigned*)&v0, *(unsigned*)&v1);
    }

    float xr[32];
    {
        const float4* xp = (const float4*)(x + (size_t)n * 32);
#pragma unroll
        for (int i = 0; i < 8; i++) {
            float4 xv = __ldg(xp + i);
            xr[i * 4 + 0] = xv.x; xr[i * 4 + 1] = xv.y;
            xr[i * 4 + 2] = xv.z; xr[i * 4 + 3] = xv.w;
        }
    }

    // ---- Pass B: query + skip + folded qk ----
    unsigned long long qk2[8];
#pragma unroll 1
    for (int ct = 0; ct < 32; ct++) {
        const int ch = ct * 4;
        if ((ct & 7) == 0) {
#pragma unroll
            for (int i = 0; i < 8; i++) qk2[i] = 0ull;
        }
        F4U aq, as2;
        aq.f  = *(const float4*)&s_b[128 + ch];
        as2.f = *(const float4*)&s_b[384 + ch];
#pragma unroll
        for (int c = 0; c < 32; c++) {
            F4U w2, w4;
            w2.f = *(const float4*)&s_wq[c * 128 + ch];
            w4.f = *(const float4*)&s_ws[c * 128 + ch];
            unsigned long long b2 = pack2(xr[c]);
            fma2(aq.u[0],  b2, w2.u[0]); fma2(aq.u[1],  b2, w2.u[1]);
            fma2(as2.u[0], b2, w4.u[0]); fma2(as2.u[1], b2, w4.u[1]);
        }
        __half2 q0 = __floats2half2_rn(aq.f.x, aq.f.y);
        __half2 q1 = __floats2half2_rn(aq.f.z, aq.f.w);
        *(uint2*)&g_qryh[(size_t)n * 128 + ch] =
            make_uint2(*(unsigned*)&q0, *(unsigned*)&q1);
        *(float4*)&out[(size_t)n * 128 + ch] = as2.f;

        float qa[4] = {aq.f.x, aq.f.y, aq.f.z, aq.f.w};
#pragma unroll
        for (int u = 0; u < 4; u++) {
            unsigned long long q2 = pack2(qa[u]);
#pragma unroll
            for (int dt = 0; dt < 4; dt++) {
                F4U ekv; ekv.f = *(const float4*)&s_ekT[(ch + u) * 16 + dt * 4];
                fma2(qk2[dt * 2],     q2, ekv.u[0]);
                fma2(qk2[dt * 2 + 1], q2, ekv.u[1]);
            }
        }
        if ((ct & 7) == 7) {
            const int h = ct >> 3;
            unsigned uu[8];
#pragma unroll
            for (int i = 0; i < 8; i++) {
                F4U tmp; tmp.u[0] = qk2[i]; tmp.u[1] = 0ull;
                __half2 p = __floats2half2_rn(tmp.f.x, tmp.f.y);
                uu[i] = *(unsigned*)&p;
            }
            *(uint4*)&g_qkh[(size_t)n * 64 + h * 16] =
                make_uint4(uu[0], uu[1], uu[2], uu[3]);
            *(uint4*)&g_qkh[(size_t)n * 64 + h * 16 + 8] =
                make_uint4(uu[4], uu[5], uu[6], uu[7]);
        }
    }
    *(float4*)&g_den[(size_t)n * 4] = make_float4(0.f, 0.f, 0.f, 0.f);
}

// ---------------- K2: edge alpha (unchanged) ----------------
__global__ void __launch_bounds__(256)
k_alpha(const float* __restrict__ ea, const int* __restrict__ ei) {
    const int gw   = (blockIdx.x * blockDim.x + threadIdx.x) >> 5;
    const int lane = threadIdx.x & 31;
    const int g = lane >> 3, t = lane & 7;
    const int e = gw * 4 + g;
    if (e >= EE) return;
    const int src = ei[e];
    const int dst = ei[EE + e];
    const int h = t >> 1, half = t & 1;

    const uint4* qp = (const uint4*)(g_qryh + (size_t)dst * 128 + h * 32 + half * 16);
    const uint4* kp = (const uint4*)(g_keyh + (size_t)src * 128 + h * 32 + half * 16);
    float s = 0.f;
#pragma unroll
    for (int b = 0; b < 2; b++) {
        uint4 qv = qp[b], kv = kp[b];
        const __half2* qh = (const __half2*)&qv;
        const __half2* kh = (const __half2*)&kv;
#pragma unroll
        for (int i = 0; i < 4; i++) {
            float2 q2 = __half22float2(qh[i]);
            float2 k2 = __half22float2(kh[i]);
            s += q2.x * k2.x + q2.y * k2.y;
        }
    }
    uint4 qkv = *(const uint4*)(g_qkh + (size_t)dst * 64 + h * 16 + half * 8);
    const __half2* qkh = (const __half2*)&qkv;
    const float4* eap = (const float4*)(ea + (size_t)e * 16 + half * 8);
    float4 e0 = eap[0], e1 = eap[1];
    float2 a;
    a = __half22float2(qkh[0]); s += a.x * e0.x + a.y * e0.y;
    a = __half22float2(qkh[1]); s += a.x * e0.z + a.y * e0.w;
    a = __half22float2(qkh[2]); s += a.x * e1.x + a.y * e1.y;
    a = __half22float2(qkh[3]); s += a.x * e1.z + a.y * e1.w;

    s += __shfl_xor_sync(0xffffffffu, s, 1);
    if (half == 0) {
        float ex = __expf(s * 0.17677669529663687f);  // 1/sqrt(32)
        g_ex[(size_t)e * 4 + h] = ex;
        atomicAdd(&g_den[(size_t)dst * 4 + h], ex);
    }
}

// ---------------- K3: dst-sorted message + segmented aggregation ----------------
// 8 lanes/edge-group; each group walks 8 CONTIGUOUS sorted edges, accumulating
// the message in registers; flush (RED) only when dst changes.
__global__ void __launch_bounds__(256)
k_msg(const float* __restrict__ ea, const float* __restrict__ sbf,
      const int* __restrict__ ei, const float* __restrict__ wev,
      const float* __restrict__ w_sbf0, const float* __restrict__ w_sbf1,
      float* __restrict__ out) {
    __shared__ float s_ev[16 * 128];
    __shared__ float s_sc[16 * 32];

    for (int i = threadIdx.x; i < 2048; i += 256) s_ev[i] = wev[i];
    for (int i = threadIdx.x; i < 512;  i += 256) {
        int d = i >> 5, c = i & 31;
        float s = 0.f;
#pragma unroll
        for (int m = 0; m < 32; m++) s += w_sbf0[d * 32 + m] * w_sbf1[m * 32 + c];
        s_sc[i] = s;
    }
    __syncthreads();

    const int warpid = threadIdx.x >> 5;
    const int lane   = threadIdx.x & 31;
    const int g = lane >> 3, t = lane & 7;

    const int win  = blockIdx.x * 8 + warpid;      // 25000 windows
    const int base = win * 32 + g * 8;             // this group's 8 sorted edges

    float macc[16];
    int cur_dst = -1;

#pragma unroll 1
    for (int i = 0; i < 8; i++) {
        const int e   = __ldg(&g_perm[base + i]);
        const int src = ei[e];
        const int dst = ei[EE + e];

        // lane t holds sbf elems t*8..t*8+7 of this edge (head-major 64 floats)
        const float4* sp = (const float4*)(sbf + (size_t)e * 64);
        float4 s0 = sp[t * 2];
        float4 s1 = sp[t * 2 + 1];
        // lane t holds ea elems t*2, t*2+1
        float2 eav = ((const float2*)(ea + (size_t)e * 16))[t];

        float4 exv = *(const float4*)&g_ex[(size_t)e * 4];
        float4 dnv = *(const float4*)&g_den[(size_t)dst * 4];

        const size_t vbase = (size_t)src * 128;
        uint2 vh[4];
#pragma unroll
        for (int j = 0; j < 4; j++)
            vh[j] = *(const uint2*)&g_valh[vbase + j * 32 + t * 4];

        // segment flush on dst change (uniform within the 8-lane group)
        if (dst != cur_dst) {
            if (cur_dst >= 0) {
                const size_t obase = (size_t)cur_dst * 128;
#pragma unroll
                for (int j = 0; j < 4; j++) {
                    float* op = out + obase + j * 32 + t * 4;
                    asm volatile("red.global.add.v4.f32 [%0], {%1,%2,%3,%4};"
                                 :: "l"(op), "f"(macc[j*4+0]), "f"(macc[j*4+1]),
                                    "f"(macc[j*4+2]), "f"(macc[j*4+3]) : "memory");
                }
            }
            cur_dst = dst;
#pragma unroll
            for (int k = 0; k < 16; k++) macc[k] = 0.f;
        }

        float al[4];
        al[0] = __fdividef(exv.x, dnv.x + 1e-16f);
        al[1] = __fdividef(exv.y, dnv.y + 1e-16f);
        al[2] = __fdividef(exv.z, dnv.z + 1e-16f);
        al[3] = __fdividef(exv.w, dnv.w + 1e-16f);

        // ev (ea @ Wev) and af (sbf @ Wsc) accumulation; per-edge scalars via shfl
        unsigned long long ev2[8], af2[8];
#pragma unroll
        for (int k = 0; k < 8; k++) { ev2[k] = 0ull; af2[k] = 0ull; }
#pragma unroll
        for (int d = 0; d < 16; d++) {
            float svo = (d & 1) ? eav.y : eav.x;
            float sv  = __shfl_sync(0xffffffffu, svo, g * 8 + (d >> 1));
            unsigned long long sv2 = pack2(sv);
            F4U w2; w2.f = *(const float4*)&s_sc[d * 32 + t * 4];
            float cmp;
            switch (d & 7) {
                case 0: cmp = s0.x; break; case 1: cmp = s0.y; break;
                case 2: cmp = s0.z; break; case 3: cmp = s0.w; break;
                case 4: cmp = s1.x; break; case 5: cmp = s1.y; break;
                case 6: cmp = s1.z; break; default: cmp = s1.w; break;
            }
#pragma unroll
            for (int j = 0; j < 4; j++) {
                // sbf elem j*16+d lives on lane g*8 + j*2 + (d>>3), component d&7
                float sbv = __shfl_sync(0xffffffffu, cmp, g * 8 + j * 2 + (d >> 3));
                unsigned long long sb2 = pack2(sbv);
                F4U w1; w1.f = *(const float4*)&s_ev[d * 128 + j * 32 + t * 4];
                fma2(ev2[j * 2],     sv2, w1.u[0]);
                fma2(ev2[j * 2 + 1], sv2, w1.u[1]);
                fma2(af2[j * 2],     sb2, w2.u[0]);
                fma2(af2[j * 2 + 1], sb2, w2.u[1]);
            }
        }

        // message -> segment accumulator
#pragma unroll
        for (int j = 0; j < 4; j++) {
            F4U ev, af;
            ev.u[0] = ev2[j * 2]; ev.u[1] = ev2[j * 2 + 1];
            af.u[0] = af2[j * 2]; af.u[1] = af2[j * 2 + 1];
            float2 vlo = __half22float2(*(const __half2*)&vh[j].x);
            float2 vhi = __half22float2(*(const __half2*)&vh[j].y);
            const float aj = al[j];
            macc[j * 4 + 0] += (vlo.x + ev.f.x) * aj * af.f.x;
            macc[j * 4 + 1] += (vlo.y + ev.f.y) * aj * af.f.y;
            macc[j * 4 + 2] += (vhi.x + ev.f.z) * aj * af.f.z;
            macc[j * 4 + 3] += (vhi.y + ev.f.w) * aj * af.f.w;
        }
    }

    // final flush
    if (cur_dst >= 0) {
        const size_t obase = (size_t)cur_dst * 128;
#pragma unroll
        for (int j = 0; j < 4; j++) {
            float* op = out + obase + j * 32 + t * 4;
            asm volatile("red.global.add.v4.f32 [%0], {%1,%2,%3,%4};"
                         :: "l"(op), "f"(macc[j*4+0]), "f"(macc[j*4+1]),
                            "f"(macc[j*4+2]), "f"(macc[j*4+3]) : "memory");
        }
    }
}

// ---------------- launcher ----------------
extern "C" void kernel_launch(void* const* d_in, const int* in_sizes, int n_in,
                              void* d_out, int out_size) {
    const float* x        = (const float*)d_in[0];
    const float* edge_attr= (const float*)d_in[1];
    const float* rbf      = (const float*)d_in[2];
    const float* sbf      = (const float*)d_in[3];
    const float* w_rbf0   = (const float*)d_in[4];
    const float* w_rbf1   = (const float*)d_in[5];
    const float* w_sbf0   = (const float*)d_in[6];
    const float* w_sbf1   = (const float*)d_in[7];
    const float* w_ek     = (const float*)d_in[8];
    const float* w_ev     = (const float*)d_in[9];
    const float* w_k      = (const float*)d_in[10];
    const float* b_k      = (const float*)d_in[11];
    const float* w_q      = (const float*)d_in[12];
    const float* b_q      = (const float*)d_in[13];
    const float* w_v      = (const float*)d_in[14];
    const float* b_v      = (const float*)d_in[15];
    const float* w_skip   = (const float*)d_in[16];
    const float* b_skip   = (const float*)d_in[17];
    const int*   edge_index = (const int*)d_in[18];
    float* out = (float*)d_out;

    const size_t k1_smem = K1_SMEM_FLOATS * sizeof(float);
    cudaFuncSetAttribute(k_node, cudaFuncAttributeMaxDynamicSharedMemorySize, (int)k1_smem);

    // counting sort of edges by destination
    k_zero<<<391, 256>>>();
    k_hist<<<3125, 256>>>(edge_index);
    k_scan1<<<SCAN_BLOCKS, 1024>>>();
    k_scan2<<<SCAN_BLOCKS, 1024>>>();
    k_scatter<<<3125, 256>>>(edge_index);

    const int k1_blocks = (NN / 32 + 7) / 8;   // 391
    k_node<<<k1_blocks, 256, k1_smem>>>(
        x, rbf, w_rbf0, w_rbf1, w_k, b_k, w_q, b_q, w_v, b_v,
        w_skip, b_skip, w_ek, out);

    k_alpha<<<EE / 4 / 8, 256>>>(edge_attr, edge_index);

    k_msg<<<3125, 256>>>(edge_attr, sbf, edge_index, w_ev,
                         w_sbf0, w_sbf1, out);
}

// round 12
// speedup vs baseline: 1.1748x; 1.1103x over previous
#include <cuda_runtime.h>
#include <cuda_fp16.h>
#include <cstdint>
#include <cstddef>

#define NN 100000
#define EE 800000
#define NTILES (EE / 4)

// ---------------- packed f32x2 helpers ----------------
union F4U { float4 f; unsigned long long u[2]; };

__device__ __forceinline__ unsigned long long pack2(float a) {
    unsigned long long r;
    asm("mov.b64 %0, {%1,%1};" : "=l"(r) : "f"(a));
    return r;
}
__device__ __forceinline__ void fma2(unsigned long long& d,
                                     unsigned long long a,
                                     unsigned long long b) {
    asm("fma.rn.f32x2 %0, %1, %2, %0;" : "+l"(d) : "l"(a), "l"(b));
}

// ---------------- device scratch (static: no runtime allocation) ----------------
__device__ __half g_keyh[(size_t)NN * 128];
__device__ __half g_qryh[(size_t)NN * 128];
__device__ __half g_qkh [(size_t)NN * 64];
__device__ __half g_valh[(size_t)NN * 128];
__device__ float  g_ex [(size_t)EE * 4];
__device__ float  g_den[(size_t)NN * 4];

// ---------------- K0: zero denominators (also occupies capture slot 1) ----------------
__global__ void k_init() {
    int i = blockIdx.x * 256 + threadIdx.x;
    if (i < NN) *(float4*)&g_den[(size_t)i * 4] = make_float4(0.f, 0.f, 0.f, 0.f);
}

// ---------------- K1: node kernel (R8-proven: 81KB smem, 2 blocks/SM) ----------------
#define K1_SMEM_FLOATS 20288

__global__ void __launch_bounds__(256, 2)
k_node(const float* __restrict__ x, const float* __restrict__ rbf,
       const float* __restrict__ w_rbf0, const float* __restrict__ w_rbf1,
       const float* __restrict__ wk, const float* __restrict__ bk,
       const float* __restrict__ wq, const float* __restrict__ bq,
       const float* __restrict__ wv, const float* __restrict__ bv,
       const float* __restrict__ wsk, const float* __restrict__ bsk,
       const float* __restrict__ wek, float* __restrict__ out) {
    extern __shared__ float sh[];
    float* s_wk  = sh;
    float* s_wq  = sh + 4096;
    float* s_wv  = sh + 8192;
    float* s_ws  = sh + 12288;
    float* s_ekT = sh + 16384;
    float* s_rc  = sh + 18432;
    float* s_b   = sh + 19776;

    const int tid = threadIdx.x;
    for (int i = tid; i < 4096; i += 256) {
        s_wk[i] = wk[i]; s_wq[i] = wq[i]; s_wv[i] = wv[i]; s_ws[i] = wsk[i];
    }
    for (int i = tid; i < 2048; i += 256) {
        int j = i >> 4, d = i & 15;
        s_ekT[i] = wek[d * 128 + j];
    }
    for (int i = tid; i < 1344; i += 256) {
        int d = i >> 5, c = i & 31;
        float s = 0.f;
#pragma unroll
        for (int m = 0; m < 32; m++) s += w_rbf0[d * 32 + m] * w_rbf1[m * 32 + c];
        s_rc[i] = s;
    }
    for (int i = tid; i < 512; i += 256) {
        int w = i >> 7, c = i & 127;
        s_b[i] = (w == 0) ? bk[c] : (w == 1) ? bq[c] : (w == 2) ? bv[c] : bsk[c];
    }
    __syncthreads();

    const int warpid = tid >> 5;
    const int lane   = tid & 31;
    const int tile   = blockIdx.x * 8 + warpid;
    if (tile >= (NN / 32)) return;
    const int n = tile * 32 + lane;

    float rr[42];
    {
        const float2* rp = (const float2*)(rbf + (size_t)n * 42);
#pragma unroll
        for (int i = 0; i < 21; i++) {
            float2 t = __ldg(rp + i);
            rr[2 * i] = t.x; rr[2 * i + 1] = t.y;
        }
    }

    F4U fil[8];
#pragma unroll
    for (int i = 0; i < 8; i++) fil[i].f = make_float4(0.f, 0.f, 0.f, 0.f);
#pragma unroll
    for (int d = 0; d < 42; d++) {
        unsigned long long r2 = pack2(rr[d]);
#pragma unroll
        for (int t8 = 0; t8 < 8; t8++) {
            F4U w; w.f = *(const float4*)&s_rc[d * 32 + t8 * 4];
            fma2(fil[t8].u[0], r2, w.u[0]);
            fma2(fil[t8].u[1], r2, w.u[1]);
        }
    }

    float xs[32];
    {
        const float4* xp = (const float4*)(x + (size_t)n * 32);
#pragma unroll
        for (int i = 0; i < 8; i++) {
            float4 xv = __ldg(xp + i);
            xs[i * 4 + 0] = fil[i].f.x * xv.x;
            xs[i * 4 + 1] = fil[i].f.y * xv.y;
            xs[i * 4 + 2] = fil[i].f.z * xv.z;
            xs[i * 4 + 3] = fil[i].f.w * xv.w;
        }
    }

    // ---- Pass A: key + value ----
#pragma unroll 1
    for (int ct = 0; ct < 32; ct++) {
        const int ch = ct * 4;
        F4U ak, av;
        ak.f = *(const float4*)&s_b[ch];
        av.f = *(const float4*)&s_b[256 + ch];
#pragma unroll
        for (int c = 0; c < 32; c++) {
            F4U w1, w3;
            w1.f = *(const float4*)&s_wk[c * 128 + ch];
            w3.f = *(const float4*)&s_wv[c * 128 + ch];
            unsigned long long a2 = pack2(xs[c]);
            fma2(ak.u[0], a2, w1.u[0]); fma2(ak.u[1], a2, w1.u[1]);
            fma2(av.u[0], a2, w3.u[0]); fma2(av.u[1], a2, w3.u[1]);
        }
        __half2 h0 = __floats2half2_rn(ak.f.x, ak.f.y);
        __half2 h1 = __floats2half2_rn(ak.f.z, ak.f.w);
        *(uint2*)&g_keyh[(size_t)n * 128 + ch] =
            make_uint2(*(unsigned*)&h0, *(unsigned*)&h1);
        __half2 v0 = __floats2half2_rn(av.f.x, av.f.y);
        __half2 v1 = __floats2half2_rn(av.f.z, av.f.w);
        *(uint2*)&g_valh[(size_t)n * 128 + ch] =
            make_uint2(*(unsigned*)&v0, *(unsigned*)&v1);
    }

    float xr[32];
    {
        const float4* xp = (const float4*)(x + (size_t)n * 32);
#pragma unroll
        for (int i = 0; i < 8; i++) {
            float4 xv = __ldg(xp + i);
            xr[i * 4 + 0] = xv.x; xr[i * 4 + 1] = xv.y;
            xr[i * 4 + 2] = xv.z; xr[i * 4 + 3] = xv.w;
        }
    }

    // ---- Pass B: query + skip + folded qk ----
    unsigned long long qk2[8];
#pragma unroll 1
    for (int ct = 0; ct < 32; ct++) {
        const int ch = ct * 4;
        if ((ct & 7) == 0) {
#pragma unroll
            for (int i = 0; i < 8; i++) qk2[i] = 0ull;
        }
        F4U aq, as2;
        aq.f  = *(const float4*)&s_b[128 + ch];
        as2.f = *(const float4*)&s_b[384 + ch];
#pragma unroll
        for (int c = 0; c < 32; c++) {
            F4U w2, w4;
            w2.f = *(const float4*)&s_wq[c * 128 + ch];
            w4.f = *(const float4*)&s_ws[c * 128 + ch];
            unsigned long long b2 = pack2(xr[c]);
            fma2(aq.u[0],  b2, w2.u[0]); fma2(aq.u[1],  b2, w2.u[1]);
            fma2(as2.u[0], b2, w4.u[0]); fma2(as2.u[1], b2, w4.u[1]);
        }
        __half2 q0 = __floats2half2_rn(aq.f.x, aq.f.y);
        __half2 q1 = __floats2half2_rn(aq.f.z, aq.f.w);
        *(uint2*)&g_qryh[(size_t)n * 128 + ch] =
            make_uint2(*(unsigned*)&q0, *(unsigned*)&q1);
        *(float4*)&out[(size_t)n * 128 + ch] = as2.f;

        float qa[4] = {aq.f.x, aq.f.y, aq.f.z, aq.f.w};
#pragma unroll
        for (int u = 0; u < 4; u++) {
            unsigned long long q2 = pack2(qa[u]);
#pragma unroll
            for (int dt = 0; dt < 4; dt++) {
                F4U ekv; ekv.f = *(const float4*)&s_ekT[(ch + u) * 16 + dt * 4];
                fma2(qk2[dt * 2],     q2, ekv.u[0]);
                fma2(qk2[dt * 2 + 1], q2, ekv.u[1]);
            }
        }
        if ((ct & 7) == 7) {
            const int h = ct >> 3;
            unsigned uu[8];
#pragma unroll
            for (int i = 0; i < 8; i++) {
                F4U tmp; tmp.u[0] = qk2[i]; tmp.u[1] = 0ull;
                __half2 p = __floats2half2_rn(tmp.f.x, tmp.f.y);
                uu[i] = *(unsigned*)&p;
            }
            *(uint4*)&g_qkh[(size_t)n * 64 + h * 16] =
                make_uint4(uu[0], uu[1], uu[2], uu[3]);
            *(uint4*)&g_qkh[(size_t)n * 64 + h * 16 + 8] =
                make_uint4(uu[4], uu[5], uu[6], uu[7]);
        }
    }
}

// ---------------- K2: edge alpha (8 lanes/edge, 4 edges/warp, fp16 gathers) ----------------
__global__ void __launch_bounds__(256)
k_alpha(const float* __restrict__ ea, const int* __restrict__ ei) {
    const int gw   = (blockIdx.x * blockDim.x + threadIdx.x) >> 5;
    const int lane = threadIdx.x & 31;
    const int g = lane >> 3, t = lane & 7;
    const int e = gw * 4 + g;
    if (e >= EE) return;
    const int src = ei[e];
    const int dst = ei[EE + e];
    const int h = t >> 1, half = t & 1;

    const uint4* qp = (const uint4*)(g_qryh + (size_t)dst * 128 + h * 32 + half * 16);
    const uint4* kp = (const uint4*)(g_keyh + (size_t)src * 128 + h * 32 + half * 16);
    float s = 0.f;
#pragma unroll
    for (int b = 0; b < 2; b++) {
        uint4 qv = qp[b], kv = kp[b];
        const __half2* qh = (const __half2*)&qv;
        const __half2* kh = (const __half2*)&kv;
#pragma unroll
        for (int i = 0; i < 4; i++) {
            float2 q2 = __half22float2(qh[i]);
            float2 k2 = __half22float2(kh[i]);
            s += q2.x * k2.x + q2.y * k2.y;
        }
    }
    uint4 qkv = *(const uint4*)(g_qkh + (size_t)dst * 64 + h * 16 + half * 8);
    const __half2* qkh = (const __half2*)&qkv;
    const float4* eap = (const float4*)(ea + (size_t)e * 16 + half * 8);
    float4 e0 = eap[0], e1 = eap[1];
    float2 a;
    a = __half22float2(qkh[0]); s += a.x * e0.x + a.y * e0.y;
    a = __half22float2(qkh[1]); s += a.x * e0.z + a.y * e0.w;
    a = __half22float2(qkh[2]); s += a.x * e1.x + a.y * e1.y;
    a = __half22float2(qkh[3]); s += a.x * e1.z + a.y * e1.w;

    s += __shfl_xor_sync(0xffffffffu, s, 1);
    if (half == 0) {
        float ex = __expf(s * 0.17677669529663687f);  // 1/sqrt(32)
        g_ex[(size_t)e * 4 + h] = ex;
        atomicAdd(&g_den[(size_t)dst * 4 + h], ex);
    }
}

// ---------------- K3: message + aggregation, double-buffered staging pipeline ----------------
__global__ void __launch_bounds__(256)
k_msg(const float* __restrict__ ea, const float* __restrict__ sbf,
      const int* __restrict__ ei, const float* __restrict__ wev,
      const float* __restrict__ w_sbf0, const float* __restrict__ w_sbf1,
      float* __restrict__ out) {
    __shared__ float s_ev[16 * 128];
    __shared__ float s_sc[16 * 32];
    __shared__ float s_buf[8][2][368];  // double-buffered per-warp staging

    for (int i = threadIdx.x; i < 2048; i += 256) s_ev[i] = wev[i];
    for (int i = threadIdx.x; i < 512;  i += 256) {
        int d = i >> 5, c = i & 31;
        float s = 0.f;
#pragma unroll
        for (int m = 0; m < 32; m++) s += w_sbf0[d * 32 + m] * w_sbf1[m * 32 + c];
        s_sc[i] = s;
    }
    __syncthreads();

    const int warpid = threadIdx.x >> 5;
    const int lane   = threadIdx.x & 31;
    const int g = lane >> 3, t = lane & 7;
    const int warps_total = gridDim.x * 8;
    const int stride = warps_total;

    int tile = blockIdx.x * 8 + warpid;

    // ---- prefetch first tile's staging data into registers ----
    float4 r_s0 = make_float4(0,0,0,0), r_s1 = make_float4(0,0,0,0), r_ea = make_float4(0,0,0,0);
    if (tile < NTILES) {
        const float4* sp = (const float4*)(sbf + (size_t)(tile * 4) * 64);
        r_s0 = __ldg(sp + lane);
        r_s1 = __ldg(sp + 32 + lane);
        if (lane < 16)
            r_ea = __ldg(((const float4*)(ea + (size_t)(tile * 4) * 16)) + lane);
    }

    int p = 0;
    while (tile < NTILES) {
        float* sb = s_buf[warpid][p];
        // ---- commit prefetched regs to smem ----
        {
            int idx = lane * 4;
            *(float4*)&sb[(idx >> 6) * 72 + (idx & 63)] = r_s0;
            idx = 128 + lane * 4;
            *(float4*)&sb[(idx >> 6) * 72 + (idx & 63)] = r_s1;
            if (lane < 16)
                *(float4*)&sb[288 + (lane >> 2) * 20 + (lane & 3) * 4] = r_ea;
        }
        __syncwarp();

        // ---- issue NEXT tile's staging loads (latency hidden under compute) ----
        const int next = tile + stride;
        if (next < NTILES) {
            const float4* sp = (const float4*)(sbf + (size_t)(next * 4) * 64);
            r_s0 = __ldg(sp + lane);
            r_s1 = __ldg(sp + 32 + lane);
            if (lane < 16)
                r_ea = __ldg(((const float4*)(ea + (size_t)(next * 4) * 16)) + lane);
        }

        const int base = tile * 4;
        const int e   = base + g;
        const int src = ei[e];
        const int dst = ei[EE + e];
        float4 exv = *(const float4*)&g_ex[(size_t)e * 4];
        float4 dnv = *(const float4*)&g_den[(size_t)dst * 4];

        // hoisted value gathers (fp16, MLP=4)
        const size_t vbase = (size_t)src * 128;
        uint2 vh[4];
#pragma unroll
        for (int j = 0; j < 4; j++)
            vh[j] = *(const uint2*)&g_valh[vbase + j * 32 + t * 4];

        float av_[4];
        av_[0] = __fdividef(exv.x, dnv.x + 1e-16f);
        av_[1] = __fdividef(exv.y, dnv.y + 1e-16f);
        av_[2] = __fdividef(exv.z, dnv.z + 1e-16f);
        av_[3] = __fdividef(exv.w, dnv.w + 1e-16f);

        unsigned long long aev2[8], af2[8];
#pragma unroll
        for (int i = 0; i < 8; i++) { aev2[i] = 0ull; af2[i] = 0ull; }
#pragma unroll 4
        for (int d = 0; d < 16; d++) {
            unsigned long long sv2 = pack2(sb[288 + g * 20 + d]);
            F4U w2; w2.f = *(const float4*)&s_sc[d * 32 + t * 4];
#pragma unroll
            for (int j = 0; j < 4; j++) {
                unsigned long long sb2 = pack2(sb[g * 72 + j * 16 + d]);
                F4U w1; w1.f = *(const float4*)&s_ev[d * 128 + j * 32 + t * 4];
                fma2(aev2[j * 2],     sv2, w1.u[0]);
                fma2(aev2[j * 2 + 1], sv2, w1.u[1]);
                fma2(af2[j * 2],      sb2, w2.u[0]);
                fma2(af2[j * 2 + 1],  sb2, w2.u[1]);
            }
        }

        const size_t obase = (size_t)dst * 128;
#pragma unroll
        for (int j = 0; j < 4; j++) {
            F4U aev, af;
            aev.u[0] = aev2[j * 2]; aev.u[1] = aev2[j * 2 + 1];
            af.u[0]  = af2[j * 2];  af.u[1]  = af2[j * 2 + 1];
            float2 vlo = __half22float2(*(const __half2*)&vh[j].x);
            float2 vhi = __half22float2(*(const __half2*)&vh[j].y);
            const float aj = av_[j];
            float mx = (vlo.x + aev.f.x) * aj * af.f.x;
            float my = (vlo.y + aev.f.y) * aj * af.f.y;
            float mz = (vhi.x + aev.f.z) * aj * af.f.z;
            float mw = (vhi.y + aev.f.w) * aj * af.f.w;
            float* op = out + obase + j * 32 + t * 4;
            asm volatile("red.global.add.v4.f32 [%0], {%1,%2,%3,%4};"
                         :: "l"(op), "f"(mx), "f"(my), "f"(mz), "f"(mw) : "memory");
        }
        __syncwarp();
        tile = next;
        p ^= 1;
    }
}

// ---------------- launcher ----------------
extern "C" void kernel_launch(void* const* d_in, const int* in_sizes, int n_in,
                              void* d_out, int out_size) {
    const float* x        = (const float*)d_in[0];
    const float* edge_attr= (const float*)d_in[1];
    const float* rbf      = (const float*)d_in[2];
    const float* sbf      = (const float*)d_in[3];
    const float* w_rbf0   = (const float*)d_in[4];
    const float* w_rbf1   = (const float*)d_in[5];
    const float* w_sbf0   = (const float*)d_in[6];
    const float* w_sbf1   = (const float*)d_in[7];
    const float* w_ek     = (const float*)d_in[8];
    const float* w_ev     = (const float*)d_in[9];
    const float* w_k      = (const float*)d_in[10];
    const float* b_k      = (const float*)d_in[11];
    const float* w_q      = (const float*)d_in[12];
    const float* b_q      = (const float*)d_in[13];
    const float* w_v      = (const float*)d_in[14];
    const float* b_v      = (const float*)d_in[15];
    const float* w_skip   = (const float*)d_in[16];
    const float* b_skip   = (const float*)d_in[17];
    const int*   edge_index = (const int*)d_in[18];
    float* out = (float*)d_out;

    const size_t k1_smem = K1_SMEM_FLOATS * sizeof(float);
    cudaFuncSetAttribute(k_node, cudaFuncAttributeMaxDynamicSharedMemorySize, (int)k1_smem);

    // launch order fixed so k_msg is the 4th global kernel launch (ncu capture slot)
    k_init<<<(NN + 255) / 256, 256>>>();

    const int k1_blocks = (NN / 32 + 7) / 8;   // 391
    k_node<<<k1_blocks, 256, k1_smem>>>(
        x, rbf, w_rbf0, w_rbf1, w_k, b_k, w_q, b_q, w_v, b_v,
        w_skip, b_skip, w_ek, out);

    k_alpha<<<EE / 4 / 8, 256>>>(edge_attr, edge_index);

    k_msg<<<1184, 256>>>(edge_attr, sbf, edge_index, w_ev,
                         w_sbf0, w_sbf1, out);
}

// round 16
// speedup vs baseline: 1.1780x; 1.0027x over previous
#include <cuda_runtime.h>
#include <cuda_fp16.h>
#include <cstdint>
#include <cstddef>

#define NN 100000
#define EE 800000
#define NTILES (EE / 4)

// ---------------- packed f32x2 helpers ----------------
union F4U { float4 f; unsigned long long u[2]; };

__device__ __forceinline__ unsigned long long pack2(float a) {
    unsigned long long r;
    asm("mov.b64 %0, {%1,%1};" : "=l"(r) : "f"(a));
    return r;
}
__device__ __forceinline__ void fma2(unsigned long long& d,
                                     unsigned long long a,
                                     unsigned long long b) {
    asm("fma.rn.f32x2 %0, %1, %2, %0;" : "+l"(d) : "l"(a), "l"(b));
}

// ---------------- device scratch (static: no runtime allocation) ----------------
__device__ __half g_keyh[(size_t)NN * 128];
__device__ __half g_qryh[(size_t)NN * 128];
__device__ __half g_qkh [(size_t)NN * 64];
__device__ __half g_valh[(size_t)NN * 128];
__device__ float  g_ex [(size_t)EE * 4];
__device__ float  g_den[(size_t)NN * 4];

// ---------------- K0: zero denominators ----------------
__global__ void k_init() {
    int i = blockIdx.x * 256 + threadIdx.x;
    if (i < NN) *(float4*)&g_den[(size_t)i * 4] = make_float4(0.f, 0.f, 0.f, 0.f);
}

// ---------------- K1: node kernel (R8-proven: 81KB smem, 2 blocks/SM) ----------------
#define K1_SMEM_FLOATS 20288

__global__ void __launch_bounds__(256, 2)
k_node(const float* __restrict__ x, const float* __restrict__ rbf,
       const float* __restrict__ w_rbf0, const float* __restrict__ w_rbf1,
       const float* __restrict__ wk, const float* __restrict__ bk,
       const float* __restrict__ wq, const float* __restrict__ bq,
       const float* __restrict__ wv, const float* __restrict__ bv,
       const float* __restrict__ wsk, const float* __restrict__ bsk,
       const float* __restrict__ wek, float* __restrict__ out) {
    extern __shared__ float sh[];
    float* s_wk  = sh;
    float* s_wq  = sh + 4096;
    float* s_wv  = sh + 8192;
    float* s_ws  = sh + 12288;
    float* s_ekT = sh + 16384;
    float* s_rc  = sh + 18432;
    float* s_b   = sh + 19776;

    const int tid = threadIdx.x;
    for (int i = tid; i < 4096; i += 256) {
        s_wk[i] = wk[i]; s_wq[i] = wq[i]; s_wv[i] = wv[i]; s_ws[i] = wsk[i];
    }
    for (int i = tid; i < 2048; i += 256) {
        int j = i >> 4, d = i & 15;
        s_ekT[i] = wek[d * 128 + j];
    }
    for (int i = tid; i < 1344; i += 256) {
        int d = i >> 5, c = i & 31;
        float s = 0.f;
#pragma unroll
        for (int m = 0; m < 32; m++) s += w_rbf0[d * 32 + m] * w_rbf1[m * 32 + c];
        s_rc[i] = s;
    }
    for (int i = tid; i < 512; i += 256) {
        int w = i >> 7, c = i & 127;
        s_b[i] = (w == 0) ? bk[c] : (w == 1) ? bq[c] : (w == 2) ? bv[c] : bsk[c];
    }
    __syncthreads();

    const int warpid = tid >> 5;
    const int lane   = tid & 31;
    const int tile   = blockIdx.x * 8 + warpid;
    if (tile >= (NN / 32)) return;
    const int n = tile * 32 + lane;

    float rr[42];
    {
        const float2* rp = (const float2*)(rbf + (size_t)n * 42);
#pragma unroll
        for (int i = 0; i < 21; i++) {
            float2 t = __ldg(rp + i);
            rr[2 * i] = t.x; rr[2 * i + 1] = t.y;
        }
    }

    F4U fil[8];
#pragma unroll
    for (int i = 0; i < 8; i++) fil[i].f = make_float4(0.f, 0.f, 0.f, 0.f);
#pragma unroll
    for (int d = 0; d < 42; d++) {
        unsigned long long r2 = pack2(rr[d]);
#pragma unroll
        for (int t8 = 0; t8 < 8; t8++) {
            F4U w; w.f = *(const float4*)&s_rc[d * 32 + t8 * 4];
            fma2(fil[t8].u[0], r2, w.u[0]);
            fma2(fil[t8].u[1], r2, w.u[1]);
        }
    }

    float xs[32];
    {
        const float4* xp = (const float4*)(x + (size_t)n * 32);
#pragma unroll
        for (int i = 0; i < 8; i++) {
            float4 xv = __ldg(xp + i);
            xs[i * 4 + 0] = fil[i].f.x * xv.x;
            xs[i * 4 + 1] = fil[i].f.y * xv.y;
            xs[i * 4 + 2] = fil[i].f.z * xv.z;
            xs[i * 4 + 3] = fil[i].f.w * xv.w;
        }
    }

    // ---- Pass A: key + value ----
#pragma unroll 1
    for (int ct = 0; ct < 32; ct++) {
        const int ch = ct * 4;
        F4U ak, av;
        ak.f = *(const float4*)&s_b[ch];
        av.f = *(const float4*)&s_b[256 + ch];
#pragma unroll
        for (int c = 0; c < 32; c++) {
            F4U w1, w3;
            w1.f = *(const float4*)&s_wk[c * 128 + ch];
            w3.f = *(const float4*)&s_wv[c * 128 + ch];
            unsigned long long a2 = pack2(xs[c]);
            fma2(ak.u[0], a2, w1.u[0]); fma2(ak.u[1], a2, w1.u[1]);
            fma2(av.u[0], a2, w3.u[0]); fma2(av.u[1], a2, w3.u[1]);
        }
        __half2 h0 = __floats2half2_rn(ak.f.x, ak.f.y);
        __half2 h1 = __floats2half2_rn(ak.f.z, ak.f.w);
        *(uint2*)&g_keyh[(size_t)n * 128 + ch] =
            make_uint2(*(unsigned*)&h0, *(unsigned*)&h1);
        __half2 v0 = __floats2half2_rn(av.f.x, av.f.y);
        __half2 v1 = __floats2half2_rn(av.f.z, av.f.w);
        *(uint2*)&g_valh[(size_t)n * 128 + ch] =
            make_uint2(*(unsigned*)&v0, *(unsigned*)&v1);
    }

    float xr[32];
    {
        const float4* xp = (const float4*)(x + (size_t)n * 32);
#pragma unroll
        for (int i = 0; i < 8; i++) {
            float4 xv = __ldg(xp + i);
            xr[i * 4 + 0] = xv.x; xr[i * 4 + 1] = xv.y;
            xr[i * 4 + 2] = xv.z; xr[i * 4 + 3] = xv.w;
        }
    }

    // ---- Pass B: query + skip + folded qk ----
    unsigned long long qk2[8];
#pragma unroll 1
    for (int ct = 0; ct < 32; ct++) {
        const int ch = ct * 4;
        if ((ct & 7) == 0) {
#pragma unroll
            for (int i = 0; i < 8; i++) qk2[i] = 0ull;
        }
        F4U aq, as2;
        aq.f  = *(const float4*)&s_b[128 + ch];
        as2.f = *(const float4*)&s_b[384 + ch];
#pragma unroll
        for (int c = 0; c < 32; c++) {
            F4U w2, w4;
            w2.f = *(const float4*)&s_wq[c * 128 + ch];
            w4.f = *(const float4*)&s_ws[c * 128 + ch];
            unsigned long long b2 = pack2(xr[c]);
            fma2(aq.u[0],  b2, w2.u[0]); fma2(aq.u[1],  b2, w2.u[1]);
            fma2(as2.u[0], b2, w4.u[0]); fma2(as2.u[1], b2, w4.u[1]);
        }
        __half2 q0 = __floats2half2_rn(aq.f.x, aq.f.y);
        __half2 q1 = __floats2half2_rn(aq.f.z, aq.f.w);
        *(uint2*)&g_qryh[(size_t)n * 128 + ch] =
            make_uint2(*(unsigned*)&q0, *(unsigned*)&q1);
        *(float4*)&out[(size_t)n * 128 + ch] = as2.f;

        float qa[4] = {aq.f.x, aq.f.y, aq.f.z, aq.f.w};
#pragma unroll
        for (int u = 0; u < 4; u++) {
            unsigned long long q2 = pack2(qa[u]);
#pragma unroll
            for (int dt = 0; dt < 4; dt++) {
                F4U ekv; ekv.f = *(const float4*)&s_ekT[(ch + u) * 16 + dt * 4];
                fma2(qk2[dt * 2],     q2, ekv.u[0]);
                fma2(qk2[dt * 2 + 1], q2, ekv.u[1]);
            }
        }
        if ((ct & 7) == 7) {
            const int h = ct >> 3;
            unsigned uu[8];
#pragma unroll
            for (int i = 0; i < 8; i++) {
                F4U tmp; tmp.u[0] = qk2[i]; tmp.u[1] = 0ull;
                __half2 p = __floats2half2_rn(tmp.f.x, tmp.f.y);
                uu[i] = *(unsigned*)&p;
            }
            *(uint4*)&g_qkh[(size_t)n * 64 + h * 16] =
                make_uint4(uu[0], uu[1], uu[2], uu[3]);
            *(uint4*)&g_qkh[(size_t)n * 64 + h * 16 + 8] =
                make_uint4(uu[4], uu[5], uu[6], uu[7]);
        }
    }
}

// ---------------- K2: edge alpha (8 lanes/edge, 4 edges/warp, fp16 gathers) ----------------
__global__ void __launch_bounds__(256)
k_alpha(const float* __restrict__ ea, const int* __restrict__ ei) {
    const int gw   = (blockIdx.x * blockDim.x + threadIdx.x) >> 5;
    const int lane = threadIdx.x & 31;
    const int g = lane >> 3, t = lane & 7;
    const int e = gw * 4 + g;
    if (e >= EE) return;
    const int src = ei[e];
    const int dst = ei[EE + e];
    const int h = t >> 1, half = t & 1;

    const uint4* qp = (const uint4*)(g_qryh + (size_t)dst * 128 + h * 32 + half * 16);
    const uint4* kp = (const uint4*)(g_keyh + (size_t)src * 128 + h * 32 + half * 16);
    float s = 0.f;
#pragma unroll
    for (int b = 0; b < 2; b++) {
        uint4 qv = qp[b], kv = kp[b];
        const __half2* qh = (const __half2*)&qv;
        const __half2* kh = (const __half2*)&kv;
#pragma unroll
        for (int i = 0; i < 4; i++) {
            float2 q2 = __half22float2(qh[i]);
            float2 k2 = __half22float2(kh[i]);
            s += q2.x * k2.x + q2.y * k2.y;
        }
    }
    uint4 qkv = *(const uint4*)(g_qkh + (size_t)dst * 64 + h * 16 + half * 8);
    const __half2* qkh = (const __half2*)&qkv;
    const float4* eap = (const float4*)(ea + (size_t)e * 16 + half * 8);
    float4 e0 = eap[0], e1 = eap[1];
    float2 a;
    a = __half22float2(qkh[0]); s += a.x * e0.x + a.y * e0.y;
    a = __half22float2(qkh[1]); s += a.x * e0.z + a.y * e0.w;
    a = __half22float2(qkh[2]); s += a.x * e1.x + a.y * e1.y;
    a = __half22float2(qkh[3]); s += a.x * e1.z + a.y * e1.w;

    s += __shfl_xor_sync(0xffffffffu, s, 1);
    if (half == 0) {
        float ex = __expf(s * 0.17677669529663687f);  // 1/sqrt(32)
        g_ex[(size_t)e * 4 + h] = ex;
        atomicAdd(&g_den[(size_t)dst * 4 + h], ex);
    }
}

// ---------------- K3: message + aggregation, double-buffered + vectorized LDS ----------------
// per-warp staging: sbf 4 edges x 64 @pitch72 (=288 floats) | ea 4 edges x 16 @pitch16 (=64)
__global__ void __launch_bounds__(256)
k_msg(const float* __restrict__ ea, const float* __restrict__ sbf,
      const int* __restrict__ ei, const float* __restrict__ wev,
      const float* __restrict__ w_sbf0, const float* __restrict__ w_sbf1,
      float* __restrict__ out) {
    __shared__ float s_ev[16 * 128];
    __shared__ float s_sc[16 * 32];
    __shared__ __align__(16) float s_buf[8][2][352];

    for (int i = threadIdx.x; i < 2048; i += 256) s_ev[i] = wev[i];
    for (int i = threadIdx.x; i < 512;  i += 256) {
        int d = i >> 5, c = i & 31;
        float s = 0.f;
#pragma unroll
        for (int m = 0; m < 32; m++) s += w_sbf0[d * 32 + m] * w_sbf1[m * 32 + c];
        s_sc[i] = s;
    }
    __syncthreads();

    const int warpid = threadIdx.x >> 5;
    const int lane   = threadIdx.x & 31;
    const int g = lane >> 3, t = lane & 7;
    const int stride = gridDim.x * 8;

    int tile = blockIdx.x * 8 + warpid;

    // ---- prefetch first tile's staging data into registers ----
    float4 r_s0 = make_float4(0,0,0,0), r_s1 = make_float4(0,0,0,0), r_ea = make_float4(0,0,0,0);
    if (tile < NTILES) {
        const float4* sp = (const float4*)(sbf + (size_t)(tile * 4) * 64);
        r_s0 = __ldg(sp + lane);
        r_s1 = __ldg(sp + 32 + lane);
        if (lane < 16)
            r_ea = __ldg(((const float4*)(ea + (size_t)(tile * 4) * 16)) + lane);
    }

    int p = 0;
    while (tile < NTILES) {
        float* sb = s_buf[warpid][p];
        // ---- commit prefetched regs to smem ----
        {
            int idx = lane * 4;
            *(float4*)&sb[(idx >> 6) * 72 + (idx & 63)] = r_s0;
            idx = 128 + lane * 4;
            *(float4*)&sb[(idx >> 6) * 72 + (idx & 63)] = r_s1;
            if (lane < 16)
                *(float4*)&sb[288 + lane * 4] = r_ea;   // ea pitch 16: edge g at 288+g*16
        }
        __syncwarp();

        // ---- issue NEXT tile's staging loads (latency hidden under compute) ----
        const int next = tile + stride;
        if (next < NTILES) {
            const float4* sp = (const float4*)(sbf + (size_t)(next * 4) * 64);
            r_s0 = __ldg(sp + lane);
            r_s1 = __ldg(sp + 32 + lane);
            if (lane < 16)
                r_ea = __ldg(((const float4*)(ea + (size_t)(next * 4) * 16)) + lane);
        }

        const int base = tile * 4;
        const int e   = base + g;
        const int src = ei[e];
        const int dst = ei[EE + e];
        float4 exv = *(const float4*)&g_ex[(size_t)e * 4];
        float4 dnv = *(const float4*)&g_den[(size_t)dst * 4];

        // hoisted value gathers (fp16, MLP=4)
        const size_t vbase = (size_t)src * 128;
        uint2 vh[4];
#pragma unroll
        for (int j = 0; j < 4; j++)
            vh[j] = *(const uint2*)&g_valh[vbase + j * 32 + t * 4];

        float av_[4];
        av_[0] = __fdividef(exv.x, dnv.x + 1e-16f);
        av_[1] = __fdividef(exv.y, dnv.y + 1e-16f);
        av_[2] = __fdividef(exv.z, dnv.z + 1e-16f);
        av_[3] = __fdividef(exv.w, dnv.w + 1e-16f);

        // accumulate edge_val (aev) and sbf_filter (af); operands via VECTOR LDS
        unsigned long long aev2[8], af2[8];
#pragma unroll
        for (int i = 0; i < 8; i++) { aev2[i] = 0ull; af2[i] = 0ull; }
#pragma unroll
        for (int dt = 0; dt < 4; dt++) {
            // 1 LDS.128: ea[e][dt*4..dt*4+3] (broadcast within group)
            float4 sv4 = *(const float4*)&sb[288 + g * 16 + dt * 4];
            // 4 LDS.128: sbf[e][j][dt*4..dt*4+3]
            float4 sb4[4];
#pragma unroll
            for (int j = 0; j < 4; j++)
                sb4[j] = *(const float4*)&sb[g * 72 + j * 16 + dt * 4];
            const float* sv4f = (const float*)&sv4;
#pragma unroll
            for (int dd = 0; dd < 4; dd++) {
                const int d = dt * 4 + dd;
                unsigned long long sv2 = pack2(sv4f[dd]);
                F4U w2; w2.f = *(const float4*)&s_sc[d * 32 + t * 4];
#pragma unroll
                for (int j = 0; j < 4; j++) {
                    unsigned long long sb2 = pack2(((const float*)&sb4[j])[dd]);
                    F4U w1; w1.f = *(const float4*)&s_ev[d * 128 + j * 32 + t * 4];
                    fma2(aev2[j * 2],     sv2, w1.u[0]);
                    fma2(aev2[j * 2 + 1], sv2, w1.u[1]);
                    fma2(af2[j * 2],      sb2, w2.u[0]);
                    fma2(af2[j * 2 + 1],  sb2, w2.u[1]);
                }
            }
        }

        const size_t obase = (size_t)dst * 128;
#pragma unroll
        for (int j = 0; j < 4; j++) {
            F4U aev, af;
            aev.u[0] = aev2[j * 2]; aev.u[1] = aev2[j * 2 + 1];
            af.u[0]  = af2[j * 2];  af.u[1]  = af2[j * 2 + 1];
            float2 vlo = __half22float2(*(const __half2*)&vh[j].x);
            float2 vhi = __half22float2(*(const __half2*)&vh[j].y);
            const float aj = av_[j];
            float mx = (vlo.x + aev.f.x) * aj * af.f.x;
            float my = (vlo.y + aev.f.y) * aj * af.f.y;
            float mz = (vhi.x + aev.f.z) * aj * af.f.z;
            float mw = (vhi.y + aev.f.w) * aj * af.f.w;
            float* op = out + obase + j * 32 + t * 4;
            asm volatile("red.global.add.v4.f32 [%0], {%1,%2,%3,%4};"
                         :: "l"(op), "f"(mx), "f"(my), "f"(mz), "f"(mw) : "memory");
        }
        __syncwarp();
        tile = next;
        p ^= 1;
    }
}

// ---------------- launcher ----------------
extern "C" void kernel_launch(void* const* d_in, const int* in_sizes, int n_in,
                              void* d_out, int out_size) {
    const float* x        = (const float*)d_in[0];
    const float* edge_attr= (const float*)d_in[1];
    const float* rbf      = (const float*)d_in[2];
    const float* sbf      = (const float*)d_in[3];
    const float* w_rbf0   = (const float*)d_in[4];
    const float* w_rbf1   = (const float*)d_in[5];
    const float* w_sbf0   = (const float*)d_in[6];
    const float* w_sbf1   = (const float*)d_in[7];
    const float* w_ek     = (const float*)d_in[8];
    const float* w_ev     = (const float*)d_in[9];
    const float* w_k      = (const float*)d_in[10];
    const float* b_k      = (const float*)d_in[11];
    const float* w_q      = (const float*)d_in[12];
    const float* b_q      = (const float*)d_in[13];
    const float* w_v      = (const float*)d_in[14];
    const float* b_v      = (const float*)d_in[15];
    const float* w_skip   = (const float*)d_in[16];
    const float* b_skip   = (const float*)d_in[17];
    const int*   edge_index = (const int*)d_in[18];
    float* out = (float*)d_out;

    const size_t k1_smem = K1_SMEM_FLOATS * sizeof(float);
    cudaFuncSetAttribute(k_node, cudaFuncAttributeMaxDynamicSharedMemorySize, (int)k1_smem);

    // launch order keeps k_msg in the ncu capture slot (4th launch)
    k_init<<<(NN + 255) / 256, 256>>>();

    const int k1_blocks = (NN / 32 + 7) / 8;   // 391
    k_node<<<k1_blocks, 256, k1_smem>>>(
        x, rbf, w_rbf0, w_rbf1, w_k, b_k, w_q, b_q, w_v, b_v,
        w_skip, b_skip, w_ek, out);

    k_alpha<<<EE / 4 / 8, 256>>>(edge_attr, edge_index);

    k_msg<<<1184, 256>>>(edge_attr, sbf, edge_index, w_ev,
                         w_sbf0, w_sbf1, out);
}